// round 16
// baseline (speedup 1.0000x reference)
#include <cuda_runtime.h>
#include <cuda_bf16.h>
#include <mma.h>

using namespace nvcuda;

// ---------------------------------------------------------------------------
// StateUpdate: scatter-mean(bonds)->[G,128], scatter-mean(sites)->[G,128],
// concat with states -> [G,384], then 3x (Linear + ReLU).
//
// R16: exact R15 (best=304.7) + ONE isolated delta: scatter_priv inner
// loop unrolled x4 -> 4 independent LDG->ATOMS->STG chains per thread
// (ATOMS result latency rt+30 was the serial bottleneck; issue was 10.5%).
// ---------------------------------------------------------------------------

namespace {
constexpr int G    = 8192;
constexpr int F    = 128;
constexpr int NBND = 2000000;
constexpr int NSIT = 500000;
constexpr int VW   = 384;
constexpr int NC   = 128;
}

__device__ int   d_hist[2][NC][G];
__device__ int   d_tot[2][G];
__device__ int   d_off[2][G + 1];
__device__ int   d_bond_sorted[NBND];
__device__ int   d_site_sorted[NSIT];
__device__ float d_V [(long)G * VW];
__device__ float d_H1[(long)G * 256];
__device__ float d_H2[(long)G * 256];

// ---------------------------------------------------------------------------
__global__ __launch_bounds__(1024) void hist_priv(
    const int* __restrict__ g2b, int nb,
    const int* __restrict__ g2s, int ns) {
    __shared__ int h[G];
    int which = blockIdx.y;
    const int* idx = which ? g2s : g2b;
    int n = which ? ns : nb;
    int cta = blockIdx.x;
    int tid = threadIdx.x;

    for (int j = tid; j < G; j += 1024) h[j] = 0;
    __syncthreads();

    int per = (n + NC - 1) / NC;
    int s = cta * per;
    int e = s + per; if (e > n) e = n;
    for (int i = s + tid; i < e; i += 1024) atomicAdd(&h[idx[i]], 1);
    __syncthreads();

    for (int j = tid; j < G; j += 1024) d_hist[which][cta][j] = h[j];
}

__global__ __launch_bounds__(256) void col_scan() {
    int g = blockIdx.x * 256 + threadIdx.x;
    int which = blockIdx.y;
    int acc = 0;
#pragma unroll 4
    for (int c = 0; c < NC; c++) {
        int v = d_hist[which][c][g];
        d_hist[which][c][g] = acc;
        acc += v;
    }
    d_tot[which][g] = acc;
}

__global__ __launch_bounds__(256) void scan_kernel() {
    __shared__ int wsum[8];
    int which = blockIdx.x;
    const int* cnt = d_tot[which];
    int* off = d_off[which];
    int t = threadIdx.x, lane = t & 31, w = t >> 5;
    int base = t * 32;

    int local[32];
    int s = 0;
#pragma unroll
    for (int i = 0; i < 32; i++) { local[i] = s; s += cnt[base + i]; }

    int inc = s;
#pragma unroll
    for (int d = 1; d < 32; d <<= 1) {
        int v = __shfl_up_sync(0xFFFFFFFFu, inc, d);
        if (lane >= d) inc += v;
    }
    if (lane == 31) wsum[w] = inc;
    __syncthreads();
    if (w == 0) {
        int v = (lane < 8) ? wsum[lane] : 0;
        int wi = v;
#pragma unroll
        for (int d = 1; d < 8; d <<= 1) {
            int u = __shfl_up_sync(0xFFFFFFFFu, wi, d);
            if (lane >= d) wi += u;
        }
        if (lane < 8) wsum[lane] = wi - v;
    }
    __syncthreads();
    int thread_excl = wsum[w] + inc - s;
#pragma unroll
    for (int i = 0; i < 32; i++) off[base + i] = thread_excl + local[i];
    if (t == 255) off[G] = thread_excl + s;
}

__global__ __launch_bounds__(1024) void scatter_priv(
    const int* __restrict__ g2b, int nb,
    const int* __restrict__ g2s, int ns) {
    __shared__ int cur[G];
    int which = blockIdx.y;
    const int* idx = which ? g2s : g2b;
    int* outp = which ? d_site_sorted : d_bond_sorted;
    int n = which ? ns : nb;
    int cta = blockIdx.x;
    int tid = threadIdx.x;

    for (int j = tid; j < G; j += 1024)
        cur[j] = d_off[which][j] + d_hist[which][cta][j];
    __syncthreads();

    int per = (n + NC - 1) / NC;
    int s = cta * per;
    int e = s + per; if (e > n) e = n;

    int i = s + tid;
    // x4 unrolled: 4 independent LDG->ATOMS->STG chains in flight
    for (; i + 3072 < e; i += 4096) {
        int g0 = __ldcs(&idx[i]);
        int g1 = __ldcs(&idx[i + 1024]);
        int g2 = __ldcs(&idx[i + 2048]);
        int g3 = __ldcs(&idx[i + 3072]);
        int p0 = atomicAdd(&cur[g0], 1);
        int p1 = atomicAdd(&cur[g1], 1);
        int p2 = atomicAdd(&cur[g2], 1);
        int p3 = atomicAdd(&cur[g3], 1);
        outp[p0] = i;
        outp[p1] = i + 1024;
        outp[p2] = i + 2048;
        outp[p3] = i + 3072;
    }
    for (; i < e; i += 1024) {
        int g = __ldcs(&idx[i]);
        int p = atomicAdd(&cur[g], 1);
        outp[p] = i;
    }
}

// ---------------------------------------------------------------------------
__device__ __forceinline__ void v4add(float4& a, const float4& v) {
    a.x += v.x; a.y += v.y; a.z += v.z; a.w += v.w;
}

// 8 independent loads in flight, folded into 4 accumulators.
__device__ __forceinline__ void seg_mean_v4(
    const float* __restrict__ data, const int* __restrict__ sorted,
    int s, int e, int tid, int lane, int w,
    int* sidx, float* sred, float* outp) {

    float4 a0 = make_float4(0.f,0.f,0.f,0.f), a1 = a0, a2 = a0, a3 = a0;

    for (int base = s; base < e; base += 256) {
        int m = e - base; if (m > 256) m = 256;
        __syncthreads();
        if (tid < m) sidx[tid] = sorted[base + tid];
        __syncthreads();
        int j = w;
        for (; j + 56 < m; j += 64) {
            float4 v0 = __ldcs(&((const float4*)(data + (long)sidx[j]      * F))[lane]);
            float4 v1 = __ldcs(&((const float4*)(data + (long)sidx[j + 8]  * F))[lane]);
            float4 v2 = __ldcs(&((const float4*)(data + (long)sidx[j + 16] * F))[lane]);
            float4 v3 = __ldcs(&((const float4*)(data + (long)sidx[j + 24] * F))[lane]);
            float4 v4 = __ldcs(&((const float4*)(data + (long)sidx[j + 32] * F))[lane]);
            float4 v5 = __ldcs(&((const float4*)(data + (long)sidx[j + 40] * F))[lane]);
            float4 v6 = __ldcs(&((const float4*)(data + (long)sidx[j + 48] * F))[lane]);
            float4 v7 = __ldcs(&((const float4*)(data + (long)sidx[j + 56] * F))[lane]);
            v4add(a0, v0); v4add(a1, v1); v4add(a2, v2); v4add(a3, v3);
            v4add(a0, v4); v4add(a1, v5); v4add(a2, v6); v4add(a3, v7);
        }
        for (; j + 24 < m; j += 32) {
            float4 v0 = __ldcs(&((const float4*)(data + (long)sidx[j]      * F))[lane]);
            float4 v1 = __ldcs(&((const float4*)(data + (long)sidx[j + 8]  * F))[lane]);
            float4 v2 = __ldcs(&((const float4*)(data + (long)sidx[j + 16] * F))[lane]);
            float4 v3 = __ldcs(&((const float4*)(data + (long)sidx[j + 24] * F))[lane]);
            v4add(a0, v0); v4add(a1, v1); v4add(a2, v2); v4add(a3, v3);
        }
        for (; j < m; j += 8) {
            float4 v0 = __ldcs(&((const float4*)(data + (long)sidx[j] * F))[lane]);
            v4add(a0, v0);
        }
    }
    v4add(a0, a1); v4add(a2, a3); v4add(a0, a2);

    __syncthreads();
    *(float4*)&sred[w * F + lane * 4] = a0;
    __syncthreads();
    if (tid < F) {
        float sum = 0.f;
#pragma unroll
        for (int ww = 0; ww < 8; ww++) sum += sred[ww * F + tid];
        int c = e - s;
        outp[tid] = sum / (float)(c > 0 ? c : 1);
    }
}

// grid (G, 2): y=0 -> bonds mean into V[:,0:128); y=1 -> sites mean into
// V[:,128:256) plus states copy into V[:,256:384).
__global__ __launch_bounds__(256) void pool_kernel(
    const float* __restrict__ bonds,
    const float* __restrict__ sites,
    const float* __restrict__ states) {
    __shared__ int   sidx[256];
    __shared__ float sred[8 * F];
    int g = blockIdx.x;
    int which = blockIdx.y;
    int tid = threadIdx.x, lane = tid & 31, w = tid >> 5;
    long vb = (long)g * VW;

    if (which == 0) {
        seg_mean_v4(bonds, d_bond_sorted, d_off[0][g], d_off[0][g + 1],
                    tid, lane, w, sidx, sred, &d_V[vb]);
    } else {
        seg_mean_v4(sites, d_site_sorted, d_off[1][g], d_off[1][g + 1],
                    tid, lane, w, sidx, sred, &d_V[vb + 128]);
        if (tid < F) d_V[vb + 256 + tid] = states[(long)g * F + tid];
    }
}

// ---------------------------------------------------------------------------
// bf16x3 wmma GEMM (R6, unchanged): C[M,N] = relu(A[M,K] @ W[N,K]^T + bias).
// BM=128, BN=64, BK=16. 8 warps in 4(m) x 2(n); warp tile 32x32 = 2x2 wmma.
namespace wg {
constexpr int BM = 128, BN = 64, BK = 16;
constexpr int LDA = 24;
constexpr int LDB = 24;
constexpr int LDC = 68;
constexpr int TILE_BYTES = (BM * LDA + BM * LDA + BN * LDB + BN * LDB) * 2;
constexpr int CSM_BYTES  = BM * LDC * 4;
constexpr int SMEM_BYTES = (TILE_BYTES > CSM_BYTES ? TILE_BYTES : CSM_BYTES);
}

__global__ __launch_bounds__(256) void gemm_wmma3(
    const float* __restrict__ A, const float* __restrict__ W,
    const float* __restrict__ bias, float* __restrict__ C,
    int M, int N, int K) {
    using namespace wg;
    __shared__ __align__(16) char smem_raw[SMEM_BYTES];
    __nv_bfloat16* Ahi = (__nv_bfloat16*)smem_raw;
    __nv_bfloat16* Alo = Ahi + BM * LDA;
    __nv_bfloat16* Bhi = Alo + BM * LDA;
    __nv_bfloat16* Blo = Bhi + BN * LDB;
    float* Csm = (float*)smem_raw;

    int tid = threadIdx.x;
    int w = tid >> 5;
    int wm = w >> 1, wn = w & 1;          // 4m x 2n warps
    int m0 = blockIdx.y * BM, n0 = blockIdx.x * BN;

    wmma::fragment<wmma::accumulator, 16, 16, 16, float> acc[2][2];
#pragma unroll
    for (int i = 0; i < 2; i++)
#pragma unroll
        for (int j = 0; j < 2; j++) wmma::fill_fragment(acc[i][j], 0.f);

    for (int k0 = 0; k0 < K; k0 += BK) {
        // fill A tile (128x16): 512 float4, 2 per thread
#pragma unroll
        for (int t = 0; t < 2; t++) {
            int i4 = tid + t * 256;
            int r = i4 >> 2, cg = (i4 & 3) * 4;
            float4 v = *(const float4*)&A[(long)(m0 + r) * K + k0 + cg];
            float vv[4] = {v.x, v.y, v.z, v.w};
#pragma unroll
            for (int q = 0; q < 4; q++) {
                __nv_bfloat16 h = __float2bfloat16(vv[q]);
                Ahi[r * LDA + cg + q] = h;
                Alo[r * LDA + cg + q] =
                    __float2bfloat16(vv[q] - __bfloat162float(h));
            }
        }
        // fill W tile (64x16): 256 float4, 1 per thread
        {
            int r = tid >> 2, cg = (tid & 3) * 4;
            float4 v = *(const float4*)&W[(long)(n0 + r) * K + k0 + cg];
            float vv[4] = {v.x, v.y, v.z, v.w};
#pragma unroll
            for (int q = 0; q < 4; q++) {
                __nv_bfloat16 h = __float2bfloat16(vv[q]);
                Bhi[r * LDB + cg + q] = h;
                Blo[r * LDB + cg + q] =
                    __float2bfloat16(vv[q] - __bfloat162float(h));
            }
        }
        __syncthreads();

        wmma::fragment<wmma::matrix_a, 16, 16, 16, __nv_bfloat16,
                       wmma::row_major> ah[2], al[2];
        wmma::fragment<wmma::matrix_b, 16, 16, 16, __nv_bfloat16,
                       wmma::col_major> bh[2], bl[2];
#pragma unroll
        for (int i = 0; i < 2; i++) {
            int mr = wm * 32 + i * 16;
            wmma::load_matrix_sync(ah[i], Ahi + mr * LDA, LDA);
            wmma::load_matrix_sync(al[i], Alo + mr * LDA, LDA);
        }
#pragma unroll
        for (int j = 0; j < 2; j++) {
            int nr = wn * 32 + j * 16;
            wmma::load_matrix_sync(bh[j], Bhi + nr * LDB, LDB);
            wmma::load_matrix_sync(bl[j], Blo + nr * LDB, LDB);
        }
#pragma unroll
        for (int i = 0; i < 2; i++)
#pragma unroll
            for (int j = 0; j < 2; j++) {
                wmma::mma_sync(acc[i][j], ah[i], bh[j], acc[i][j]);
                wmma::mma_sync(acc[i][j], ah[i], bl[j], acc[i][j]);
                wmma::mma_sync(acc[i][j], al[i], bh[j], acc[i][j]);
            }
        __syncthreads();
    }

    // epilogue: stage C in smem, then coalesced bias+relu float4 stores
#pragma unroll
    for (int i = 0; i < 2; i++)
#pragma unroll
        for (int j = 0; j < 2; j++)
            wmma::store_matrix_sync(
                Csm + (wm * 32 + i * 16) * LDC + wn * 32 + j * 16,
                acc[i][j], LDC, wmma::mem_row_major);
    __syncthreads();

#pragma unroll
    for (int t = 0; t < (BM * BN / 4) / 256; t++) {
        int i4 = tid + t * 256;
        int r = i4 / (BN / 4), c4 = (i4 % (BN / 4)) * 4;
        float4 v = *(const float4*)&Csm[r * LDC + c4];
        float4 bv = *(const float4*)&bias[n0 + c4];
        float4 o;
        o.x = v.x + bv.x; o.y = v.y + bv.y;
        o.z = v.z + bv.z; o.w = v.w + bv.w;
        o.x = o.x > 0.f ? o.x : 0.f;
        o.y = o.y > 0.f ? o.y : 0.f;
        o.z = o.z > 0.f ? o.z : 0.f;
        o.w = o.w > 0.f ? o.w : 0.f;
        *(float4*)&C[(long)(m0 + r) * N + n0 + c4] = o;
    }
}

// ---------------------------------------------------------------------------
extern "C" void kernel_launch(void* const* d_in, const int* in_sizes, int n_in,
                              void* d_out, int out_size) {
    const float* sites  = (const float*)d_in[0];
    const float* bonds  = (const float*)d_in[1];
    const float* states = (const float*)d_in[2];
    const int*   g2s    = (const int*)d_in[3];
    const int*   g2b    = (const int*)d_in[4];
    const float* W1 = (const float*)d_in[5];
    const float* b1 = (const float*)d_in[6];
    const float* W2 = (const float*)d_in[7];
    const float* b2 = (const float*)d_in[8];
    const float* W3 = (const float*)d_in[9];
    const float* b3 = (const float*)d_in[10];
    float* out = (float*)d_out;

    int ns = in_sizes[3];
    int nb = in_sizes[4];

    void *pV, *pH1, *pH2;
    cudaGetSymbolAddress(&pV,  d_V);
    cudaGetSymbolAddress(&pH1, d_H1);
    cudaGetSymbolAddress(&pH2, d_H2);

    hist_priv<<<dim3(NC, 2), 1024>>>(g2b, nb, g2s, ns);
    col_scan<<<dim3(G / 256, 2), 256>>>();
    scan_kernel<<<2, 256>>>();
    scatter_priv<<<dim3(NC, 2), 1024>>>(g2b, nb, g2s, ns);

    pool_kernel<<<dim3(G, 2), 256>>>(bonds, sites, states);

    gemm_wmma3<<<dim3(256 / 64, G / 128), 256>>>((const float*)pV,  W1, b1, (float*)pH1, G, 256, 384);
    gemm_wmma3<<<dim3(256 / 64, G / 128), 256>>>((const float*)pH1, W2, b2, (float*)pH2, G, 256, 256);
    gemm_wmma3<<<dim3(128 / 64, G / 128), 256>>>((const float*)pH2, W3, b3, out,         G, 128, 256);
}

// round 17
// speedup vs baseline: 1.0138x; 1.0138x over previous
#include <cuda_runtime.h>
#include <cuda_bf16.h>
#include <mma.h>

using namespace nvcuda;

// ---------------------------------------------------------------------------
// StateUpdate: scatter-mean(bonds)->[G,128], scatter-mean(sites)->[G,128],
// concat with states -> [G,384], then 3x (Linear + ReLU).
//
// R17: exact R15 (best=304.7; scatter unroll reverted — measured neutral,
// store-stream bound) + ONE isolated delta: hist_priv idx reads vectorized
// to int4 (4x fewer LDGs). Chunk size aligned to 4 in BOTH hist and scatter
// so boundaries stay identical.
// ---------------------------------------------------------------------------

namespace {
constexpr int G    = 8192;
constexpr int F    = 128;
constexpr int NBND = 2000000;
constexpr int NSIT = 500000;
constexpr int VW   = 384;
constexpr int NC   = 128;
}

__device__ int   d_hist[2][NC][G];
__device__ int   d_tot[2][G];
__device__ int   d_off[2][G + 1];
__device__ int   d_bond_sorted[NBND];
__device__ int   d_site_sorted[NSIT];
__device__ float d_V [(long)G * VW];
__device__ float d_H1[(long)G * 256];
__device__ float d_H2[(long)G * 256];

__device__ __forceinline__ int chunk_per(int n) {
    int p = (n + NC - 1) / NC;
    return (p + 3) & ~3;                 // 4-element aligned chunk starts
}

// ---------------------------------------------------------------------------
__global__ __launch_bounds__(1024) void hist_priv(
    const int* __restrict__ g2b, int nb,
    const int* __restrict__ g2s, int ns) {
    __shared__ int h[G];
    int which = blockIdx.y;
    const int* idx = which ? g2s : g2b;
    int n = which ? ns : nb;
    int cta = blockIdx.x;
    int tid = threadIdx.x;

    for (int j = tid; j < G; j += 1024) h[j] = 0;
    __syncthreads();

    int per = chunk_per(n);
    int s = cta * per;
    int e = s + per; if (e > n) e = n;
    if (s < e) {
        int m = e - s;
        int m4 = m >> 2;                 // int4 loads (s is 4-aligned)
        const int4* idx4 = (const int4*)(idx + s);
        for (int i = tid; i < m4; i += 1024) {
            int4 v = __ldcs(&idx4[i]);
            atomicAdd(&h[v.x], 1);
            atomicAdd(&h[v.y], 1);
            atomicAdd(&h[v.z], 1);
            atomicAdd(&h[v.w], 1);
        }
        for (int i = s + m4 * 4 + tid; i < e; i += 1024)
            atomicAdd(&h[idx[i]], 1);
    }
    __syncthreads();

    for (int j = tid; j < G; j += 1024) d_hist[which][cta][j] = h[j];
}

__global__ __launch_bounds__(256) void col_scan() {
    int g = blockIdx.x * 256 + threadIdx.x;
    int which = blockIdx.y;
    int acc = 0;
#pragma unroll 4
    for (int c = 0; c < NC; c++) {
        int v = d_hist[which][c][g];
        d_hist[which][c][g] = acc;
        acc += v;
    }
    d_tot[which][g] = acc;
}

__global__ __launch_bounds__(256) void scan_kernel() {
    __shared__ int wsum[8];
    int which = blockIdx.x;
    const int* cnt = d_tot[which];
    int* off = d_off[which];
    int t = threadIdx.x, lane = t & 31, w = t >> 5;
    int base = t * 32;

    int local[32];
    int s = 0;
#pragma unroll
    for (int i = 0; i < 32; i++) { local[i] = s; s += cnt[base + i]; }

    int inc = s;
#pragma unroll
    for (int d = 1; d < 32; d <<= 1) {
        int v = __shfl_up_sync(0xFFFFFFFFu, inc, d);
        if (lane >= d) inc += v;
    }
    if (lane == 31) wsum[w] = inc;
    __syncthreads();
    if (w == 0) {
        int v = (lane < 8) ? wsum[lane] : 0;
        int wi = v;
#pragma unroll
        for (int d = 1; d < 8; d <<= 1) {
            int u = __shfl_up_sync(0xFFFFFFFFu, wi, d);
            if (lane >= d) wi += u;
        }
        if (lane < 8) wsum[lane] = wi - v;
    }
    __syncthreads();
    int thread_excl = wsum[w] + inc - s;
#pragma unroll
    for (int i = 0; i < 32; i++) off[base + i] = thread_excl + local[i];
    if (t == 255) off[G] = thread_excl + s;
}

__global__ __launch_bounds__(1024) void scatter_priv(
    const int* __restrict__ g2b, int nb,
    const int* __restrict__ g2s, int ns) {
    __shared__ int cur[G];
    int which = blockIdx.y;
    const int* idx = which ? g2s : g2b;
    int* outp = which ? d_site_sorted : d_bond_sorted;
    int n = which ? ns : nb;
    int cta = blockIdx.x;
    int tid = threadIdx.x;

    for (int j = tid; j < G; j += 1024)
        cur[j] = d_off[which][j] + d_hist[which][cta][j];
    __syncthreads();

    int per = chunk_per(n);
    int s = cta * per;
    int e = s + per; if (e > n) e = n;
    for (int i = s + tid; i < e; i += 1024) {
        int g = __ldcs(&idx[i]);
        int p = atomicAdd(&cur[g], 1);
        outp[p] = i;
    }
}

// ---------------------------------------------------------------------------
__device__ __forceinline__ void v4add(float4& a, const float4& v) {
    a.x += v.x; a.y += v.y; a.z += v.z; a.w += v.w;
}

// 8 independent loads in flight, folded into 4 accumulators.
__device__ __forceinline__ void seg_mean_v4(
    const float* __restrict__ data, const int* __restrict__ sorted,
    int s, int e, int tid, int lane, int w,
    int* sidx, float* sred, float* outp) {

    float4 a0 = make_float4(0.f,0.f,0.f,0.f), a1 = a0, a2 = a0, a3 = a0;

    for (int base = s; base < e; base += 256) {
        int m = e - base; if (m > 256) m = 256;
        __syncthreads();
        if (tid < m) sidx[tid] = sorted[base + tid];
        __syncthreads();
        int j = w;
        for (; j + 56 < m; j += 64) {
            float4 v0 = __ldcs(&((const float4*)(data + (long)sidx[j]      * F))[lane]);
            float4 v1 = __ldcs(&((const float4*)(data + (long)sidx[j + 8]  * F))[lane]);
            float4 v2 = __ldcs(&((const float4*)(data + (long)sidx[j + 16] * F))[lane]);
            float4 v3 = __ldcs(&((const float4*)(data + (long)sidx[j + 24] * F))[lane]);
            float4 v4 = __ldcs(&((const float4*)(data + (long)sidx[j + 32] * F))[lane]);
            float4 v5 = __ldcs(&((const float4*)(data + (long)sidx[j + 40] * F))[lane]);
            float4 v6 = __ldcs(&((const float4*)(data + (long)sidx[j + 48] * F))[lane]);
            float4 v7 = __ldcs(&((const float4*)(data + (long)sidx[j + 56] * F))[lane]);
            v4add(a0, v0); v4add(a1, v1); v4add(a2, v2); v4add(a3, v3);
            v4add(a0, v4); v4add(a1, v5); v4add(a2, v6); v4add(a3, v7);
        }
        for (; j + 24 < m; j += 32) {
            float4 v0 = __ldcs(&((const float4*)(data + (long)sidx[j]      * F))[lane]);
            float4 v1 = __ldcs(&((const float4*)(data + (long)sidx[j + 8]  * F))[lane]);
            float4 v2 = __ldcs(&((const float4*)(data + (long)sidx[j + 16] * F))[lane]);
            float4 v3 = __ldcs(&((const float4*)(data + (long)sidx[j + 24] * F))[lane]);
            v4add(a0, v0); v4add(a1, v1); v4add(a2, v2); v4add(a3, v3);
        }
        for (; j < m; j += 8) {
            float4 v0 = __ldcs(&((const float4*)(data + (long)sidx[j] * F))[lane]);
            v4add(a0, v0);
        }
    }
    v4add(a0, a1); v4add(a2, a3); v4add(a0, a2);

    __syncthreads();
    *(float4*)&sred[w * F + lane * 4] = a0;
    __syncthreads();
    if (tid < F) {
        float sum = 0.f;
#pragma unroll
        for (int ww = 0; ww < 8; ww++) sum += sred[ww * F + tid];
        int c = e - s;
        outp[tid] = sum / (float)(c > 0 ? c : 1);
    }
}

// grid (G, 2): y=0 -> bonds mean into V[:,0:128); y=1 -> sites mean into
// V[:,128:256) plus states copy into V[:,256:384).
__global__ __launch_bounds__(256) void pool_kernel(
    const float* __restrict__ bonds,
    const float* __restrict__ sites,
    const float* __restrict__ states) {
    __shared__ int   sidx[256];
    __shared__ float sred[8 * F];
    int g = blockIdx.x;
    int which = blockIdx.y;
    int tid = threadIdx.x, lane = tid & 31, w = tid >> 5;
    long vb = (long)g * VW;

    if (which == 0) {
        seg_mean_v4(bonds, d_bond_sorted, d_off[0][g], d_off[0][g + 1],
                    tid, lane, w, sidx, sred, &d_V[vb]);
    } else {
        seg_mean_v4(sites, d_site_sorted, d_off[1][g], d_off[1][g + 1],
                    tid, lane, w, sidx, sred, &d_V[vb + 128]);
        if (tid < F) d_V[vb + 256 + tid] = states[(long)g * F + tid];
    }
}

// ---------------------------------------------------------------------------
// bf16x3 wmma GEMM (R6, unchanged): C[M,N] = relu(A[M,K] @ W[N,K]^T + bias).
// BM=128, BN=64, BK=16. 8 warps in 4(m) x 2(n); warp tile 32x32 = 2x2 wmma.
namespace wg {
constexpr int BM = 128, BN = 64, BK = 16;
constexpr int LDA = 24;
constexpr int LDB = 24;
constexpr int LDC = 68;
constexpr int TILE_BYTES = (BM * LDA + BM * LDA + BN * LDB + BN * LDB) * 2;
constexpr int CSM_BYTES  = BM * LDC * 4;
constexpr int SMEM_BYTES = (TILE_BYTES > CSM_BYTES ? TILE_BYTES : CSM_BYTES);
}

__global__ __launch_bounds__(256) void gemm_wmma3(
    const float* __restrict__ A, const float* __restrict__ W,
    const float* __restrict__ bias, float* __restrict__ C,
    int M, int N, int K) {
    using namespace wg;
    __shared__ __align__(16) char smem_raw[SMEM_BYTES];
    __nv_bfloat16* Ahi = (__nv_bfloat16*)smem_raw;
    __nv_bfloat16* Alo = Ahi + BM * LDA;
    __nv_bfloat16* Bhi = Alo + BM * LDA;
    __nv_bfloat16* Blo = Bhi + BN * LDB;
    float* Csm = (float*)smem_raw;

    int tid = threadIdx.x;
    int w = tid >> 5;
    int wm = w >> 1, wn = w & 1;          // 4m x 2n warps
    int m0 = blockIdx.y * BM, n0 = blockIdx.x * BN;

    wmma::fragment<wmma::accumulator, 16, 16, 16, float> acc[2][2];
#pragma unroll
    for (int i = 0; i < 2; i++)
#pragma unroll
        for (int j = 0; j < 2; j++) wmma::fill_fragment(acc[i][j], 0.f);

    for (int k0 = 0; k0 < K; k0 += BK) {
        // fill A tile (128x16): 512 float4, 2 per thread
#pragma unroll
        for (int t = 0; t < 2; t++) {
            int i4 = tid + t * 256;
            int r = i4 >> 2, cg = (i4 & 3) * 4;
            float4 v = *(const float4*)&A[(long)(m0 + r) * K + k0 + cg];
            float vv[4] = {v.x, v.y, v.z, v.w};
#pragma unroll
            for (int q = 0; q < 4; q++) {
                __nv_bfloat16 h = __float2bfloat16(vv[q]);
                Ahi[r * LDA + cg + q] = h;
                Alo[r * LDA + cg + q] =
                    __float2bfloat16(vv[q] - __bfloat162float(h));
            }
        }
        // fill W tile (64x16): 256 float4, 1 per thread
        {
            int r = tid >> 2, cg = (tid & 3) * 4;
            float4 v = *(const float4*)&W[(long)(n0 + r) * K + k0 + cg];
            float vv[4] = {v.x, v.y, v.z, v.w};
#pragma unroll
            for (int q = 0; q < 4; q++) {
                __nv_bfloat16 h = __float2bfloat16(vv[q]);
                Bhi[r * LDB + cg + q] = h;
                Blo[r * LDB + cg + q] =
                    __float2bfloat16(vv[q] - __bfloat162float(h));
            }
        }
        __syncthreads();

        wmma::fragment<wmma::matrix_a, 16, 16, 16, __nv_bfloat16,
                       wmma::row_major> ah[2], al[2];
        wmma::fragment<wmma::matrix_b, 16, 16, 16, __nv_bfloat16,
                       wmma::col_major> bh[2], bl[2];
#pragma unroll
        for (int i = 0; i < 2; i++) {
            int mr = wm * 32 + i * 16;
            wmma::load_matrix_sync(ah[i], Ahi + mr * LDA, LDA);
            wmma::load_matrix_sync(al[i], Alo + mr * LDA, LDA);
        }
#pragma unroll
        for (int j = 0; j < 2; j++) {
            int nr = wn * 32 + j * 16;
            wmma::load_matrix_sync(bh[j], Bhi + nr * LDB, LDB);
            wmma::load_matrix_sync(bl[j], Blo + nr * LDB, LDB);
        }
#pragma unroll
        for (int i = 0; i < 2; i++)
#pragma unroll
            for (int j = 0; j < 2; j++) {
                wmma::mma_sync(acc[i][j], ah[i], bh[j], acc[i][j]);
                wmma::mma_sync(acc[i][j], ah[i], bl[j], acc[i][j]);
                wmma::mma_sync(acc[i][j], al[i], bh[j], acc[i][j]);
            }
        __syncthreads();
    }

    // epilogue: stage C in smem, then coalesced bias+relu float4 stores
#pragma unroll
    for (int i = 0; i < 2; i++)
#pragma unroll
        for (int j = 0; j < 2; j++)
            wmma::store_matrix_sync(
                Csm + (wm * 32 + i * 16) * LDC + wn * 32 + j * 16,
                acc[i][j], LDC, wmma::mem_row_major);
    __syncthreads();

#pragma unroll
    for (int t = 0; t < (BM * BN / 4) / 256; t++) {
        int i4 = tid + t * 256;
        int r = i4 / (BN / 4), c4 = (i4 % (BN / 4)) * 4;
        float4 v = *(const float4*)&Csm[r * LDC + c4];
        float4 bv = *(const float4*)&bias[n0 + c4];
        float4 o;
        o.x = v.x + bv.x; o.y = v.y + bv.y;
        o.z = v.z + bv.z; o.w = v.w + bv.w;
        o.x = o.x > 0.f ? o.x : 0.f;
        o.y = o.y > 0.f ? o.y : 0.f;
        o.z = o.z > 0.f ? o.z : 0.f;
        o.w = o.w > 0.f ? o.w : 0.f;
        *(float4*)&C[(long)(m0 + r) * N + n0 + c4] = o;
    }
}

// ---------------------------------------------------------------------------
extern "C" void kernel_launch(void* const* d_in, const int* in_sizes, int n_in,
                              void* d_out, int out_size) {
    const float* sites  = (const float*)d_in[0];
    const float* bonds  = (const float*)d_in[1];
    const float* states = (const float*)d_in[2];
    const int*   g2s    = (const int*)d_in[3];
    const int*   g2b    = (const int*)d_in[4];
    const float* W1 = (const float*)d_in[5];
    const float* b1 = (const float*)d_in[6];
    const float* W2 = (const float*)d_in[7];
    const float* b2 = (const float*)d_in[8];
    const float* W3 = (const float*)d_in[9];
    const float* b3 = (const float*)d_in[10];
    float* out = (float*)d_out;

    int ns = in_sizes[3];
    int nb = in_sizes[4];

    void *pV, *pH1, *pH2;
    cudaGetSymbolAddress(&pV,  d_V);
    cudaGetSymbolAddress(&pH1, d_H1);
    cudaGetSymbolAddress(&pH2, d_H2);

    hist_priv<<<dim3(NC, 2), 1024>>>(g2b, nb, g2s, ns);
    col_scan<<<dim3(G / 256, 2), 256>>>();
    scan_kernel<<<2, 256>>>();
    scatter_priv<<<dim3(NC, 2), 1024>>>(g2b, nb, g2s, ns);

    pool_kernel<<<dim3(G, 2), 256>>>(bonds, sites, states);

    gemm_wmma3<<<dim3(256 / 64, G / 128), 256>>>((const float*)pV,  W1, b1, (float*)pH1, G, 256, 384);
    gemm_wmma3<<<dim3(256 / 64, G / 128), 256>>>((const float*)pH1, W2, b2, (float*)pH2, G, 256, 256);
    gemm_wmma3<<<dim3(128 / 64, G / 128), 256>>>((const float*)pH2, W3, b3, out,         G, 128, 256);
}